// round 4
// baseline (speedup 1.0000x reference)
#include <cuda_runtime.h>

typedef unsigned long long u64;
typedef unsigned int u32;

#define TPB    128
#define EPW    4                    // elements per warp
#define EPB    16                   // elements per tile
#define TILES  2                    // tiles per block (amortize LUT build)
#define TROW   36                   // words per t-row (32 data slots + 4)
#define IMG    1012                 // 28*36 + 4 : 1012 % 32 == 20 -> e-quarter bank spread
#define XW     (EPB * IMG)          // 16192 words
#define BYTEW  (4 * 256 * 10)       // byte-LUT: [p4][byte][j], 10240 words
#define NIBW   (8 * 16 * 10)        // nibble scratch, 1280 words
#define SMEMW  (XW + BYTEW + NIBW)  // 27712 words = 110848 B -> 2 blocks/SM

// ---- packed fp32x2 helpers (sm_103a dual-fp32: 2x FFMA throughput) ----
__device__ __forceinline__ u64 pk(float lo, float hi) {
    u64 r; asm("mov.b64 %0, {%1, %2};" : "=l"(r) : "f"(lo), "f"(hi)); return r;
}
__device__ __forceinline__ void upk(float& lo, float& hi, u64 v) {
    asm("mov.b64 {%0, %1}, %2;" : "=f"(lo), "=f"(hi) : "l"(v));
}
__device__ __forceinline__ u64 fma2(u64 a, u64 b, u64 c) {
    u64 d; asm("fma.rn.f32x2 %0, %1, %2, %3;" : "=l"(d) : "l"(a), "l"(b), "l"(c)); return d;
}
__device__ __forceinline__ u64 add2(u64 a, u64 b) {
    u64 d; asm("add.rn.f32x2 %0, %1, %2;" : "=l"(d) : "l"(a), "l"(b)); return d;
}

extern __shared__ __align__(16) float smem_f[];

__global__ void __launch_bounds__(TPB, 2) snn_kernel(
    const float* __restrict__ x,  const float* __restrict__ W1,
    const float* __restrict__ b1, const float* __restrict__ W2,
    const float* __restrict__ b2, float* __restrict__ out, int B)
{
    float* smx  = smem_f;               // staged x tiles (swizzled, t-major)
    float* tabB = smem_f + XW;          // byte-LUT
    float* nib  = tabB + BYTEW;         // nibble scratch

    const int tid = threadIdx.x;
    const int lid = tid & 31;
    const int wid = tid >> 5;
    const int q   = lid >> 3;           // elem within warp (0..3)
    const int r   = lid & 7;            // unit-slice (0..7)
    const int eLocal = wid * EPW + q;

    // ======== nibble tables: nib[(p*16+v)*10 + j] = sum_{b in v} W2[j][4p+b] ========
    for (int idx = tid; idx < NIBW; idx += TPB) {
        int j = idx % 10;
        int v = (idx / 10) & 15;
        int p = idx / 160;
        float s = 0.0f;
#pragma unroll
        for (int b = 0; b < 4; ++b)
            if ((v >> b) & 1) s += W2[j * 32 + 4 * p + b];
        nib[idx] = s;
    }
    __syncthreads();

    // ======== byte-LUT: tabB[(p4*256+vv)*10 + j] = nib_lo[vv&15] + nib_hi[vv>>4] ====
    for (int idx = tid; idx < BYTEW; idx += TPB) {
        int j  = idx % 10;
        int vv = (idx / 10) & 255;
        int p4 = idx / 2560;
        tabB[idx] = nib[((2 * p4) * 16 + (vv & 15)) * 10 + j]
                  + nib[((2 * p4 + 1) * 16 + (vv >> 4)) * 10 + j];
    }

    // ======== per-lane register weights: unit-pairs (r, r+16) and (r+8, r+24) ======
    u64 wA[28], wB[28];
    {
        const float4* p0 = reinterpret_cast<const float4*>(W1 + r * 28);
        const float4* p1 = reinterpret_cast<const float4*>(W1 + (r + 16) * 28);
        const float4* p2 = reinterpret_cast<const float4*>(W1 + (r + 8) * 28);
        const float4* p3 = reinterpret_cast<const float4*>(W1 + (r + 24) * 28);
#pragma unroll
        for (int c = 0; c < 7; ++c) {
            float4 a = __ldg(p0 + c), b = __ldg(p1 + c);
            float4 e = __ldg(p2 + c), f = __ldg(p3 + c);
            wA[4 * c + 0] = pk(a.x, b.x); wA[4 * c + 1] = pk(a.y, b.y);
            wA[4 * c + 2] = pk(a.z, b.z); wA[4 * c + 3] = pk(a.w, b.w);
            wB[4 * c + 0] = pk(e.x, f.x); wB[4 * c + 1] = pk(e.y, f.y);
            wB[4 * c + 2] = pk(e.z, f.z); wB[4 * c + 3] = pk(e.w, f.w);
        }
    }
    const u64 hb0 = pk(__ldg(&b1[r]),     __ldg(&b1[r + 16]));
    const u64 hb1 = pk(__ldg(&b1[r + 8]), __ldg(&b1[r + 24]));

    // layer-2 lane roles: lanes 0..19 -> (elem me, output-pair jj)
    const int jj = lid % 5;
    const int me = (lid / 5) & 3;
    const u64 b2p = pk(__ldg(&b2[2 * jj]), __ldg(&b2[2 * jj + 1]));
    const float* tj = tabB + 2 * jj;
    const u32 sel = (u32)me | (((u32)me + 4) << 4);   // byte_perm: pick byte 'me' of a,b

#pragma unroll 1
    for (int tile = 0; tile < TILES; ++tile) {
        const int gbase = (blockIdx.x * TILES + tile) * EPB;

        __syncthreads();   // previous tile fully consumed; LUT build done (tile 0)

        // ==== stage x: contiguous LDG.128 (4 lines/warp-load), XOR-swizzled STS ====
        // float4 F covers (e, i, t = 4c..4c+3); stored at row t, word (i ^ 4c).
        for (int F = tid; F < EPB * 196; F += TPB) {
            int e = F / 196, r2 = F - e * 196;
            int i = r2 / 7,  c  = r2 - i * 7;
            if (gbase + e < B) {
                float4 v = __ldg(reinterpret_cast<const float4*>(
                    x + (size_t)(gbase + e) * 784 + i * 28 + 4 * c));
                float* d = smx + e * IMG + 4 * c * TROW + (i ^ (4 * c));
                d[0] = v.x; d[TROW] = v.y; d[2 * TROW] = v.z; d[3 * TROW] = v.w;
            }
        }
        __syncthreads();

        // ==== main recurrence over t ====
        u64 v1a = 0ull, v1b = 0ull, v2p = 0ull, accp = 0ull;
        const float* xbase = smx + eLocal * IMG;

#pragma unroll 2
        for (int t = 0; t < 28; ++t) {
            const float* xrow = xbase + t * TROW;
            const int m4 = (t >> 2) * 4;          // chunk swizzle key

            // ---- layer 1: two sequential fma2 chains (units packed (u,u+16)) ----
            u64 h0 = hb0, h1 = hb1;
#pragma unroll
            for (int k = 0; k < 7; ++k) {
                float4 xv = *reinterpret_cast<const float4*>(xrow + ((4 * k) ^ m4));
                u64 d0 = pk(xv.x, xv.x);
                h0 = fma2(d0, wA[4 * k + 0], h0); h1 = fma2(d0, wB[4 * k + 0], h1);
                u64 d1 = pk(xv.y, xv.y);
                h0 = fma2(d1, wA[4 * k + 1], h0); h1 = fma2(d1, wB[4 * k + 1], h1);
                u64 d2 = pk(xv.z, xv.z);
                h0 = fma2(d2, wA[4 * k + 2], h0); h1 = fma2(d2, wB[4 * k + 2], h1);
                u64 d3 = pk(xv.w, xv.w);
                h0 = fma2(d3, wA[4 * k + 3], h0); h1 = fma2(d3, wB[4 * k + 3], h1);
            }

            // ---- IF layer 1 + spike ballots ----
            v1a = add2(v1a, h0);
            v1b = add2(v1b, h1);
            float fa0, fa1, fb0, fb1;
            upk(fa0, fa1, v1a);
            upk(fb0, fb1, v1b);
            bool sr0  = (fa0 >= 1.0f);      // unit r
            bool sr16 = (fa1 >= 1.0f);      // unit r+16
            bool sr8  = (fb0 >= 1.0f);      // unit r+8
            bool sr24 = (fb1 >= 1.0f);      // unit r+24
            u32 B0 = __ballot_sync(0xffffffffu, sr0);
            u32 B1 = __ballot_sync(0xffffffffu, sr8);
            u32 B2 = __ballot_sync(0xffffffffu, sr16);
            u32 B3 = __ballot_sync(0xffffffffu, sr24);
            v1a = pk(sr0 ? 0.0f : fa0, sr16 ? 0.0f : fa1);
            v1b = pk(sr8 ? 0.0f : fb0, sr24 ? 0.0f : fb1);

            // ---- 32-bit spike mask of elem 'me' via 3 PRMTs (bit k = unit k) ----
            u32 lo16 = __byte_perm(B0, B1, sel);
            u32 hi16 = __byte_perm(B2, B3, sel);
            u32 M    = __byte_perm(lo16, hi16, 0x5410);

            // ---- layer 2: byte-LUT, 4 lookups (packed j-pair) ----
            u64 h2 = b2p;
            h2 = add2(h2, *reinterpret_cast<const u64*>(tj + (M & 0xffu) * 10));
            h2 = add2(h2, *reinterpret_cast<const u64*>(tj + ((M >> 8)  & 0xffu) * 10 + 2560));
            h2 = add2(h2, *reinterpret_cast<const u64*>(tj + ((M >> 16) & 0xffu) * 10 + 5120));
            h2 = add2(h2, *reinterpret_cast<const u64*>(tj + (M >> 24) * 10 + 7680));

            // ---- IF layer 2 + rate accumulation ----
            v2p = add2(v2p, h2);
            float g0, g1;
            upk(g0, g1, v2p);
            bool t0 = (g0 >= 1.0f), t1 = (g1 >= 1.0f);
            accp = add2(accp, pk(t0 ? 1.0f : 0.0f, t1 ? 1.0f : 0.0f));
            v2p = pk(t0 ? 0.0f : g0, t1 ? 0.0f : g1);
        }

        // ---- output: lanes 0..19 write their (elem, j-pair) firing rates ----
        int ge = gbase + wid * EPW + me;
        if (lid < 20 && ge < B) {
            float a0, a1;
            upk(a0, a1, accp);
            *reinterpret_cast<float2*>(out + (size_t)ge * 10 + 2 * jj) =
                make_float2(a0 * (1.0f / 28.0f), a1 * (1.0f / 28.0f));
        }
    }
}

extern "C" void kernel_launch(void* const* d_in, const int* in_sizes, int n_in,
                              void* d_out, int out_size) {
    const float* x  = (const float*)d_in[0];
    const float* W1 = (const float*)d_in[1];
    const float* b1 = (const float*)d_in[2];
    const float* W2 = (const float*)d_in[3];
    const float* b2 = (const float*)d_in[4];
    float* out = (float*)d_out;

    int B = in_sizes[0] / 784;
    int smem = SMEMW * (int)sizeof(float);   // 110,848 B -> 2 blocks/SM (8 warps)

    cudaFuncSetAttribute(snn_kernel, cudaFuncAttributeMaxDynamicSharedMemorySize, smem);

    int grid = (B + EPB * TILES - 1) / (EPB * TILES);
    snn_kernel<<<grid, TPB, smem>>>(x, W1, b1, W2, b2, out, B);
}

// round 6
// speedup vs baseline: 1.5201x; 1.5201x over previous
#include <cuda_runtime.h>

typedef unsigned long long u64;
typedef unsigned int u32;

#define TPB   128
#define EPW   4                     // elements per warp
#define EPB   16                    // elements per block
#define IMGR  812                   // words per staged elem; 812%32=12, %4=0
#define HOFF  400                   // word offset of i-half 1; (400-1)%32=15 -> group spread
#define XW    (EPB * IMGR)          // 12992 words
#define LUTW  (8 * 16 * 16)         // LUT [p][v][16]: 2048 words (8 KB)
#define SMEMW (XW + LUTW)           // 15040 words = 60160 B -> 3 blocks/SM

// ---- packed fp32x2 helpers (sm_103a dual-fp32: 2x FFMA throughput) ----
__device__ __forceinline__ u64 pk(float lo, float hi) {
    u64 r; asm("mov.b64 %0, {%1, %2};" : "=l"(r) : "f"(lo), "f"(hi)); return r;
}
__device__ __forceinline__ void upk(float& lo, float& hi, u64 v) {
    asm("mov.b64 {%0, %1}, %2;" : "=f"(lo), "=f"(hi) : "l"(v));
}
__device__ __forceinline__ u64 fma2(u64 a, u64 b, u64 c) {
    u64 d; asm("fma.rn.f32x2 %0, %1, %2, %3;" : "=l"(d) : "l"(a), "l"(b), "l"(c)); return d;
}
__device__ __forceinline__ u64 add2(u64 a, u64 b) {
    u64 d; asm("add.rn.f32x2 %0, %1, %2;" : "=l"(d) : "l"(a), "l"(b)); return d;
}
__device__ __forceinline__ u64 shfl64x(u64 v, int m) {
    float lo, hi; upk(lo, hi, v);
    lo = __shfl_xor_sync(0xffffffffu, lo, m);
    hi = __shfl_xor_sync(0xffffffffu, hi, m);
    return pk(lo, hi);
}

extern __shared__ __align__(16) float smem_f[];

__global__ void __launch_bounds__(TPB, 3) snn_kernel(
    const float* __restrict__ x,  const float* __restrict__ W1,
    const float* __restrict__ b1, const float* __restrict__ W2,
    const float* __restrict__ b2, float* __restrict__ out, int B)
{
    float* smx = smem_f;            // staged x, i-major, per-elem halves at 0 / HOFF
    float* tab = smem_f + XW;       // nibble LUT [(p*16+v)*16 + j]

    const int tid = threadIdx.x;
    const int lid = tid & 31;
    const int wid = tid >> 5;
    const int e   = lid >> 3;       // elem within warp (0..3)
    const int bh  = (lid >> 2) & 1; // pipeline half (0: i<14 prefix, 1: i>=14 finisher)
    const int a   = lid & 3;        // unit-group: owns units 8a..8a+7
    const int eLocal = wid * EPW + e;            // <-- R5 bug fixed
    const int gbase  = blockIdx.x * EPB;

    // ======== nibble LUT: tab[(p*16+v)*16 + j] = sum_{bit in v} W2[j][4p+bit] ======
    for (int idx = tid; idx < LUTW; idx += TPB) {
        int j = idx & 15;
        int v = (idx >> 4) & 15;
        int p = idx >> 8;
        float s = 0.0f;
        if (j < 10) {
#pragma unroll
            for (int bb = 0; bb < 4; ++bb)
                if ((v >> bb) & 1) s += W2[j * 32 + 4 * p + bb];
        }
        tab[idx] = s;
    }

    // ======== stage x: contiguous float4 memcpy (coalesced LDG, conflict-free STS) ==
    for (int F = tid; F < EPB * 196; F += TPB) {
        int ee = F / 196, w = F - ee * 196;
        if (gbase + ee < B) {
            float4 v = __ldg(reinterpret_cast<const float4*>(
                x + (size_t)(gbase + ee) * 784 + 4 * w));
            *reinterpret_cast<float4*>(smx + ee * IMGR + 4 * w + 8 * (w >= 98)) = v;
        }
    }

    // ======== per-lane register weights: units 8a..8a+7, i in [14*bh, 14*bh+14) =====
    u64 wr[14][4];
    {
        const int i0 = 14 * bh;
#pragma unroll
        for (int m = 0; m < 4; ++m) {
            const float* r0 = W1 + (8 * a + 2 * m) * 28 + i0;
            const float* r1 = W1 + (8 * a + 2 * m + 1) * 28 + i0;
#pragma unroll
            for (int il = 0; il < 14; ++il)
                wr[il][m] = pk(__ldg(r0 + il), __ldg(r1 + il));
        }
    }
    u64 hb[4];
#pragma unroll
    for (int m = 0; m < 4; ++m)
        hb[m] = pk(__ldg(&b1[8 * a + 2 * m]), __ldg(&b1[8 * a + 2 * m + 1]));

    // layer-2 lane roles: (elem me, output-pair jj); lanes 20..31 mirror 0..11
    const int jj = lid % 5;
    const int me = (lid / 5) & 3;
    const u64 b2p = pk(__ldg(&b2[2 * jj]), __ldg(&b2[2 * jj + 1]));
    const float* tj = tab + 2 * jj;

    __syncthreads();

    // ================= pipelined main recurrence ================================
    // iter T: bh=0 computes serial prefix S_low(T)=b1+x0w..x13w for t=T;
    //         bh=1 continues x14w..x27w on shfl'd S_low(T-1)  -> EXACT serial h(T-1).
    // x address: t_lane = T - bh, folded into pointer (always in-bounds).
    const float* xq = smx + eLocal * IMGR + bh * (HOFF - 1);
    u64 h[4]  = {0ull, 0ull, 0ull, 0ull};
    u64 v1[4] = {0ull, 0ull, 0ull, 0ull};
    u64 v2p = 0ull, accp = 0ull;

#pragma unroll 1
    for (int T = 0; T <= 28; ++T) {
        // ---- hand off previous prefix to the finisher half ----
        u64 st0 = shfl64x(h[0], 4), st1 = shfl64x(h[1], 4);
        u64 st2 = shfl64x(h[2], 4), st3 = shfl64x(h[3], 4);
        h[0] = bh ? st0 : hb[0];
        h[1] = bh ? st1 : hb[1];
        h[2] = bh ? st2 : hb[2];
        h[3] = bh ? st3 : hb[3];

        // ---- 14 serial FMA2 steps (scalar LDS, 8 bcast groups, conflict-free) ----
        const float* xt = xq + T;
#pragma unroll
        for (int il = 0; il < 14; ++il) {
            float xv = xt[il * 28];
            u64 xd = pk(xv, xv);
            h[0] = fma2(xd, wr[il][0], h[0]);
            h[1] = fma2(xd, wr[il][1], h[1]);
            h[2] = fma2(xd, wr[il][2], h[2]);
            h[3] = fma2(xd, wr[il][3], h[3]);
        }

        if (T > 0) {
            // ---- IF layer 1 (valid on bh=1 lanes; bh=0 v1 is unused garbage) ----
            u32 by = 0;
#pragma unroll
            for (int m = 0; m < 4; ++m) {
                v1[m] = add2(v1[m], h[m]);
                float lo, hi; upk(lo, hi, v1[m]);
                bool sl = (lo >= 1.0f), sh = (hi >= 1.0f);
                by |= ((u32)sl << (2 * m)) | ((u32)sh << (2 * m + 1));
                v1[m] = pk(sl ? 0.0f : lo, sh ? 0.0f : hi);
            }

            // ---- gather elem 'me' mask from finisher lanes me*8+4+a ----
            u32 q0 = __shfl_sync(0xffffffffu, by, me * 8 + 4);
            u32 q1 = __shfl_sync(0xffffffffu, by, me * 8 + 5);
            u32 q2 = __shfl_sync(0xffffffffu, by, me * 8 + 6);
            u32 q3 = __shfl_sync(0xffffffffu, by, me * 8 + 7);
            u32 M  = __byte_perm(__byte_perm(q0, q1, 0x0040),
                                 __byte_perm(q2, q3, 0x0040), 0x5410);

            // ---- layer 2: 8 nibble-LUT lookups, stride 16 (shift-addressed) ----
            u64 h2 = b2p;
            h2 = add2(h2, *reinterpret_cast<const u64*>(tj + ((M << 4) & 0xF0u)));
            h2 = add2(h2, *reinterpret_cast<const u64*>(tj + ((M >> 0)  & 0xF0u) + 256));
            h2 = add2(h2, *reinterpret_cast<const u64*>(tj + ((M >> 4)  & 0xF0u) + 512));
            h2 = add2(h2, *reinterpret_cast<const u64*>(tj + ((M >> 8)  & 0xF0u) + 768));
            h2 = add2(h2, *reinterpret_cast<const u64*>(tj + ((M >> 12) & 0xF0u) + 1024));
            h2 = add2(h2, *reinterpret_cast<const u64*>(tj + ((M >> 16) & 0xF0u) + 1280));
            h2 = add2(h2, *reinterpret_cast<const u64*>(tj + ((M >> 20) & 0xF0u) + 1536));
            h2 = add2(h2, *reinterpret_cast<const u64*>(tj + ((M >> 24) & 0xF0u) + 1792));

            // ---- IF layer 2 + rate accumulation ----
            v2p = add2(v2p, h2);
            float g0, g1; upk(g0, g1, v2p);
            bool t0 = (g0 >= 1.0f), t1 = (g1 >= 1.0f);
            accp = add2(accp, pk(t0 ? 1.0f : 0.0f, t1 ? 1.0f : 0.0f));
            v2p = pk(t0 ? 0.0f : g0, t1 ? 0.0f : g1);
        }
    }

    // ---- output: lanes 0..19 write their (elem, j-pair) firing rates ----
    int ge = gbase + wid * EPW + me;
    if (lid < 20 && ge < B) {
        float a0, a1; upk(a0, a1, accp);
        *reinterpret_cast<float2*>(out + (size_t)ge * 10 + 2 * jj) =
            make_float2(a0 * (1.0f / 28.0f), a1 * (1.0f / 28.0f));
    }
}

extern "C" void kernel_launch(void* const* d_in, const int* in_sizes, int n_in,
                              void* d_out, int out_size) {
    const float* x  = (const float*)d_in[0];
    const float* W1 = (const float*)d_in[1];
    const float* b1 = (const float*)d_in[2];
    const float* W2 = (const float*)d_in[3];
    const float* b2 = (const float*)d_in[4];
    float* out = (float*)d_out;

    int B = in_sizes[0] / 784;
    int smem = SMEMW * (int)sizeof(float);   // 60,160 B -> 3 blocks/SM (12 warps)

    cudaFuncSetAttribute(snn_kernel, cudaFuncAttributeMaxDynamicSharedMemorySize, smem);

    int grid = (B + EPB - 1) / EPB;
    snn_kernel<<<grid, TPB, smem>>>(x, W1, b1, W2, b2, out, B);
}

// round 7
// speedup vs baseline: 1.8196x; 1.1971x over previous
#include <cuda_runtime.h>

typedef unsigned long long u64;
typedef unsigned int u32;

#define TPB   128
#define EPW   4                     // elements per warp
#define EPB   16                    // elements per block
#define TROW  36                    // words per t-row (32 slots + 4)
#define IMG   1012                  // 28*36+4; 1012%32=20 -> elem bank-quad spread
#define XW    (EPB * IMG)           // 16192 words
#define LUTW  (8 * 16 * 16)         // LUT [(p*16+v)*16 + j]: 2048 words (8 KB)
#define SMEMW (XW + LUTW)           // 18240 words = 72960 B -> 3 blocks/SM

// ---- packed fp32x2 helpers (sm_103a dual-fp32: 2x FFMA throughput) ----
__device__ __forceinline__ u64 pk(float lo, float hi) {
    u64 r; asm("mov.b64 %0, {%1, %2};" : "=l"(r) : "f"(lo), "f"(hi)); return r;
}
__device__ __forceinline__ void upk(float& lo, float& hi, u64 v) {
    asm("mov.b64 {%0, %1}, %2;" : "=f"(lo), "=f"(hi) : "l"(v));
}
__device__ __forceinline__ u64 fma2(u64 a, u64 b, u64 c) {
    u64 d; asm("fma.rn.f32x2 %0, %1, %2, %3;" : "=l"(d) : "l"(a), "l"(b), "l"(c)); return d;
}
__device__ __forceinline__ u64 add2(u64 a, u64 b) {
    u64 d; asm("add.rn.f32x2 %0, %1, %2;" : "=l"(d) : "l"(a), "l"(b)); return d;
}

extern __shared__ __align__(16) float smem_f[];

__global__ void __launch_bounds__(TPB, 3) snn_kernel(
    const float* __restrict__ x,  const float* __restrict__ W1,
    const float* __restrict__ b1, const float* __restrict__ W2,
    const float* __restrict__ b2, float* __restrict__ out, int B)
{
    float* smx = smem_f;            // staged x, t-major rows, XOR-swizzled words
    float* tab = smem_f + XW;       // nibble LUT

    const int tid = threadIdx.x;
    const int lid = tid & 31;
    const int wid = tid >> 5;
    const int q   = lid >> 3;       // elem within warp (0..3)
    const int r   = lid & 7;        // unit-slice (0..7)
    const int eLocal = wid * EPW + q;
    const int gbase  = blockIdx.x * EPB;

    // ======== nibble LUT: tab[(p*16+v)*16 + j] = sum_{bit in v} W2[j][4p+bit] ======
    for (int idx = tid; idx < LUTW; idx += TPB) {
        int j = idx & 15;
        int v = (idx >> 4) & 15;
        int p = idx >> 8;
        float s = 0.0f;
        if (j < 10) {
#pragma unroll
            for (int bb = 0; bb < 4; ++bb)
                if ((v >> bb) & 1) s += W2[j * 32 + 4 * p + bb];
        }
        tab[idx] = s;
    }

    // ======== stage x: contiguous LDG.128 + XOR-swizzled transpose STS ========
    // float4 F covers (e, i, t=4c..4c+3); stored at rows 4c.., word (i ^ 4c).
    for (int F = tid; F < EPB * 196; F += TPB) {
        int e = F / 196, r2 = F - e * 196;
        int i = r2 / 7,  c  = r2 - i * 7;
        if (gbase + e < B) {
            float4 v = __ldg(reinterpret_cast<const float4*>(
                x + (size_t)(gbase + e) * 784 + i * 28 + 4 * c));
            float* d = smx + e * IMG + 4 * c * TROW + (i ^ (4 * c));
            d[0] = v.x; d[TROW] = v.y; d[2 * TROW] = v.z; d[3 * TROW] = v.w;
        }
    }

    // ======== per-lane register weights: unit-pairs (r, r+16) and (r+8, r+24) ======
    u64 wA[28], wB[28];
    {
        const float4* p0 = reinterpret_cast<const float4*>(W1 + r * 28);
        const float4* p1 = reinterpret_cast<const float4*>(W1 + (r + 16) * 28);
        const float4* p2 = reinterpret_cast<const float4*>(W1 + (r + 8) * 28);
        const float4* p3 = reinterpret_cast<const float4*>(W1 + (r + 24) * 28);
#pragma unroll
        for (int c = 0; c < 7; ++c) {
            float4 a = __ldg(p0 + c), b = __ldg(p1 + c);
            float4 e = __ldg(p2 + c), f = __ldg(p3 + c);
            wA[4 * c + 0] = pk(a.x, b.x); wA[4 * c + 1] = pk(a.y, b.y);
            wA[4 * c + 2] = pk(a.z, b.z); wA[4 * c + 3] = pk(a.w, b.w);
            wB[4 * c + 0] = pk(e.x, f.x); wB[4 * c + 1] = pk(e.y, f.y);
            wB[4 * c + 2] = pk(e.z, f.z); wB[4 * c + 3] = pk(e.w, f.w);
        }
    }
    const u64 hb0 = pk(__ldg(&b1[r]),     __ldg(&b1[r + 16]));
    const u64 hb1 = pk(__ldg(&b1[r + 8]), __ldg(&b1[r + 24]));

    // layer-2 lane roles: lanes 0..19 -> (elem me, output-pair jj); 20..31 mirror
    const int jj = lid % 5;
    const int me = (lid / 5) & 3;
    const u64 b2p = pk(__ldg(&b2[2 * jj]), __ldg(&b2[2 * jj + 1]));
    const float* tj = tab + 2 * jj;
    const u32 sel = (u32)me | (((u32)me + 4) << 4);   // byte_perm: byte 'me' of a,b

    __syncthreads();

    // ================= main recurrence ==========================================
    u64 v1a = 0ull, v1b = 0ull, v2p = 0ull, accp = 0ull;
    const float* xbase = smx + eLocal * IMG;

#pragma unroll 2
    for (int t = 0; t < 28; ++t) {
        const float* xrow = xbase + t * TROW;
        const int m4 = (t >> 2) << 2;           // swizzle key for this t-quad

        // ---- layer 1: two exact sequential fma2 chains (units packed (u,u+16)) ----
        u64 h0 = hb0, h1 = hb1;
#pragma unroll
        for (int k = 0; k < 7; ++k) {
            float4 xv = *reinterpret_cast<const float4*>(xrow + ((4 * k) ^ m4));
            u64 d0 = pk(xv.x, xv.x);
            h0 = fma2(d0, wA[4 * k + 0], h0); h1 = fma2(d0, wB[4 * k + 0], h1);
            u64 d1 = pk(xv.y, xv.y);
            h0 = fma2(d1, wA[4 * k + 1], h0); h1 = fma2(d1, wB[4 * k + 1], h1);
            u64 d2 = pk(xv.z, xv.z);
            h0 = fma2(d2, wA[4 * k + 2], h0); h1 = fma2(d2, wB[4 * k + 2], h1);
            u64 d3 = pk(xv.w, xv.w);
            h0 = fma2(d3, wA[4 * k + 3], h0); h1 = fma2(d3, wB[4 * k + 3], h1);
        }

        // ---- IF layer 1 + spike ballots ----
        v1a = add2(v1a, h0);
        v1b = add2(v1b, h1);
        float fa0, fa1, fb0, fb1;
        upk(fa0, fa1, v1a);
        upk(fb0, fb1, v1b);
        bool sr0  = (fa0 >= 1.0f);      // unit r
        bool sr16 = (fa1 >= 1.0f);      // unit r+16
        bool sr8  = (fb0 >= 1.0f);      // unit r+8
        bool sr24 = (fb1 >= 1.0f);      // unit r+24
        u32 B0 = __ballot_sync(0xffffffffu, sr0);
        u32 B1 = __ballot_sync(0xffffffffu, sr8);
        u32 B2 = __ballot_sync(0xffffffffu, sr16);
        u32 B3 = __ballot_sync(0xffffffffu, sr24);
        v1a = pk(sr0 ? 0.0f : fa0, sr16 ? 0.0f : fa1);
        v1b = pk(sr8 ? 0.0f : fb0, sr24 ? 0.0f : fb1);

        // ---- 32-bit spike mask of elem 'me' via 3 PRMTs (bit k = unit k) ----
        u32 lo16 = __byte_perm(B0, B1, sel);
        u32 hi16 = __byte_perm(B2, B3, sel);
        u32 M    = __byte_perm(lo16, hi16, 0x5410);

        // ---- layer 2: 8 nibble-LUT lookups, stride 16 (shift-addressed) ----
        u64 h2 = b2p;
        h2 = add2(h2, *reinterpret_cast<const u64*>(tj + ((M << 4) & 0xF0u)));
        h2 = add2(h2, *reinterpret_cast<const u64*>(tj + ((M >> 0)  & 0xF0u) + 256));
        h2 = add2(h2, *reinterpret_cast<const u64*>(tj + ((M >> 4)  & 0xF0u) + 512));
        h2 = add2(h2, *reinterpret_cast<const u64*>(tj + ((M >> 8)  & 0xF0u) + 768));
        h2 = add2(h2, *reinterpret_cast<const u64*>(tj + ((M >> 12) & 0xF0u) + 1024));
        h2 = add2(h2, *reinterpret_cast<const u64*>(tj + ((M >> 16) & 0xF0u) + 1280));
        h2 = add2(h2, *reinterpret_cast<const u64*>(tj + ((M >> 20) & 0xF0u) + 1536));
        h2 = add2(h2, *reinterpret_cast<const u64*>(tj + ((M >> 24) & 0xF0u) + 1792));

        // ---- IF layer 2 + rate accumulation ----
        v2p = add2(v2p, h2);
        float g0, g1; upk(g0, g1, v2p);
        bool t0 = (g0 >= 1.0f), t1 = (g1 >= 1.0f);
        accp = add2(accp, pk(t0 ? 1.0f : 0.0f, t1 ? 1.0f : 0.0f));
        v2p = pk(t0 ? 0.0f : g0, t1 ? 0.0f : g1);
    }

    // ---- output: lanes 0..19 write their (elem, j-pair) firing rates ----
    int ge = gbase + wid * EPW + me;
    if (lid < 20 && ge < B) {
        float a0, a1; upk(a0, a1, accp);
        *reinterpret_cast<float2*>(out + (size_t)ge * 10 + 2 * jj) =
            make_float2(a0 * (1.0f / 28.0f), a1 * (1.0f / 28.0f));
    }
}

extern "C" void kernel_launch(void* const* d_in, const int* in_sizes, int n_in,
                              void* d_out, int out_size) {
    const float* x  = (const float*)d_in[0];
    const float* W1 = (const float*)d_in[1];
    const float* b1 = (const float*)d_in[2];
    const float* W2 = (const float*)d_in[3];
    const float* b2 = (const float*)d_in[4];
    float* out = (float*)d_out;

    int B = in_sizes[0] / 784;
    int smem = SMEMW * (int)sizeof(float);   // 72,960 B -> 3 blocks/SM (12 warps)

    cudaFuncSetAttribute(snn_kernel, cudaFuncAttributeMaxDynamicSharedMemorySize, smem);

    int grid = (B + EPB - 1) / EPB;
    snn_kernel<<<grid, TPB, smem>>>(x, W1, b1, W2, b2, out, B);
}

// round 8
// speedup vs baseline: 1.9304x; 1.0609x over previous
#include <cuda_runtime.h>

typedef unsigned long long u64;
typedef unsigned int u32;

#define TPB   128
#define EPW   4                     // elements per warp
#define EPB   16                    // elements per block
#define TROW  32                    // words per t-row (28 data + swizzle domain)
#define IMG   904                   // 28*32 + 8 skew; 904%32=8 -> elem quads disjoint
#define XW    (EPB * IMG)           // 14464 words
#define VSTR  10                    // LUT stride: 10v mod 32 distinct for v in [0,16)
#define LUTW  (8 * 16 * VSTR)       // 1280 words (5 KB)
#define SMEMW (XW + LUTW + 16)      // 15760 words = 63040 B -> 3 blocks/SM

// ---- packed fp32x2 helpers (sm_103a dual-fp32: 2x FFMA throughput) ----
__device__ __forceinline__ u64 pk(float lo, float hi) {
    u64 r; asm("mov.b64 %0, {%1, %2};" : "=l"(r) : "f"(lo), "f"(hi)); return r;
}
__device__ __forceinline__ void upk(float& lo, float& hi, u64 v) {
    asm("mov.b64 {%0, %1}, %2;" : "=f"(lo), "=f"(hi) : "l"(v));
}
__device__ __forceinline__ u64 fma2(u64 a, u64 b, u64 c) {
    u64 d; asm("fma.rn.f32x2 %0, %1, %2, %3;" : "=l"(d) : "l"(a), "l"(b), "l"(c)); return d;
}
__device__ __forceinline__ u64 add2(u64 a, u64 b) {
    u64 d; asm("add.rn.f32x2 %0, %1, %2;" : "=l"(d) : "l"(a), "l"(b)); return d;
}

extern __shared__ __align__(16) float smem_f[];

__global__ void __launch_bounds__(TPB, 3) snn_kernel(
    const float* __restrict__ x,  const float* __restrict__ W1,
    const float* __restrict__ b1, const float* __restrict__ W2,
    const float* __restrict__ b2, float* __restrict__ out, int B)
{
    float* smx = smem_f;            // staged x, t-major rows, XOR-swizzled words
    float* tab = smem_f + XW;       // nibble LUT [(p*16+v)*10 + j]

    const int tid = threadIdx.x;
    const int lid = tid & 31;
    const int wid = tid >> 5;
    const int q   = lid >> 3;       // elem within warp (0..3)
    const int r   = lid & 7;        // unit-slice (0..7)
    const int eLocal = wid * EPW + q;
    const int gbase  = blockIdx.x * EPB;

    // ======== nibble LUT: tab[(p*16+v)*10 + j] = sum_{bit in v} W2[j][4p+bit] ======
    for (int idx = tid; idx < LUTW; idx += TPB) {
        int j = idx % 10;
        int v = (idx / 10) & 15;
        int p = idx / 160;
        float s = 0.0f;
#pragma unroll
        for (int bb = 0; bb < 4; ++bb)
            if ((v >> bb) & 1) s += W2[j * 32 + 4 * p + bb];
        tab[idx] = s;
    }

    // ======== stage x: contiguous LDG.128 + XOR-swizzled transpose STS ========
    // float4 F covers (e, i, t=4c..4c+3); stored at rows 4c+k, word (i ^ 4c).
    for (int F = tid; F < EPB * 196; F += TPB) {
        int e = F / 196, r2 = F - e * 196;
        int i = r2 / 7,  c  = r2 - i * 7;
        if (gbase + e < B) {
            float4 v = __ldg(reinterpret_cast<const float4*>(
                x + (size_t)(gbase + e) * 784 + i * 28 + 4 * c));
            float* d = smx + e * IMG + 4 * c * TROW + (i ^ (4 * c));
            d[0] = v.x; d[TROW] = v.y; d[2 * TROW] = v.z; d[3 * TROW] = v.w;
        }
    }

    // ======== per-lane register weights: unit-pairs (r, r+16) and (r+8, r+24) ======
    u64 wA[28], wB[28];
    {
        const float4* p0 = reinterpret_cast<const float4*>(W1 + r * 28);
        const float4* p1 = reinterpret_cast<const float4*>(W1 + (r + 16) * 28);
        const float4* p2 = reinterpret_cast<const float4*>(W1 + (r + 8) * 28);
        const float4* p3 = reinterpret_cast<const float4*>(W1 + (r + 24) * 28);
#pragma unroll
        for (int c = 0; c < 7; ++c) {
            float4 a = __ldg(p0 + c), b = __ldg(p1 + c);
            float4 e = __ldg(p2 + c), f = __ldg(p3 + c);
            wA[4 * c + 0] = pk(a.x, b.x); wA[4 * c + 1] = pk(a.y, b.y);
            wA[4 * c + 2] = pk(a.z, b.z); wA[4 * c + 3] = pk(a.w, b.w);
            wB[4 * c + 0] = pk(e.x, f.x); wB[4 * c + 1] = pk(e.y, f.y);
            wB[4 * c + 2] = pk(e.z, f.z); wB[4 * c + 3] = pk(e.w, f.w);
        }
    }
    const u64 hb0 = pk(__ldg(&b1[r]),     __ldg(&b1[r + 16]));
    const u64 hb1 = pk(__ldg(&b1[r + 8]), __ldg(&b1[r + 24]));

    // layer-2 lane roles: lanes 0..19 -> (elem me, output-pair jj); 20..31 mirror
    const int jj = lid % 5;
    const int me = (lid / 5) & 3;
    const u64 b2p = pk(__ldg(&b2[2 * jj]), __ldg(&b2[2 * jj + 1]));
    const float* tj = tab + 2 * jj;
    const u32 sel = (u32)me | (((u32)me + 4) << 4);   // byte_perm: byte 'me' of a,b

    __syncthreads();

    // ================= main recurrence ==========================================
    u64 v1a = 0ull, v1b = 0ull, v2p = 0ull, accp = 0ull;
    const float* xbase = smx + eLocal * IMG;

#pragma unroll 2
    for (int t = 0; t < 28; ++t) {
        const float* xrow = xbase + t * TROW;
        const int m4 = (t >> 2) << 2;           // swizzle key (multiple of 4)

        // ---- layer 1: two exact sequential fma2 chains (units packed (u,u+16)) ----
        u64 h0 = hb0, h1 = hb1;
#pragma unroll
        for (int k = 0; k < 7; ++k) {
            float4 xv = *reinterpret_cast<const float4*>(xrow + ((4 * k) ^ m4));
            u64 d0 = pk(xv.x, xv.x);
            h0 = fma2(d0, wA[4 * k + 0], h0); h1 = fma2(d0, wB[4 * k + 0], h1);
            u64 d1 = pk(xv.y, xv.y);
            h0 = fma2(d1, wA[4 * k + 1], h0); h1 = fma2(d1, wB[4 * k + 1], h1);
            u64 d2 = pk(xv.z, xv.z);
            h0 = fma2(d2, wA[4 * k + 2], h0); h1 = fma2(d2, wB[4 * k + 2], h1);
            u64 d3 = pk(xv.w, xv.w);
            h0 = fma2(d3, wA[4 * k + 3], h0); h1 = fma2(d3, wB[4 * k + 3], h1);
        }

        // ---- IF layer 1 + spike ballots ----
        v1a = add2(v1a, h0);
        v1b = add2(v1b, h1);
        float fa0, fa1, fb0, fb1;
        upk(fa0, fa1, v1a);
        upk(fb0, fb1, v1b);
        bool sr0  = (fa0 >= 1.0f);      // unit r
        bool sr16 = (fa1 >= 1.0f);      // unit r+16
        bool sr8  = (fb0 >= 1.0f);      // unit r+8
        bool sr24 = (fb1 >= 1.0f);      // unit r+24
        u32 B0 = __ballot_sync(0xffffffffu, sr0);
        u32 B1 = __ballot_sync(0xffffffffu, sr8);
        u32 B2 = __ballot_sync(0xffffffffu, sr16);
        u32 B3 = __ballot_sync(0xffffffffu, sr24);
        v1a = pk(sr0 ? 0.0f : fa0, sr16 ? 0.0f : fa1);
        v1b = pk(sr8 ? 0.0f : fb0, sr24 ? 0.0f : fb1);

        // ---- 32-bit spike mask of elem 'me' via 3 PRMTs (bit k = unit k) ----
        u32 lo16 = __byte_perm(B0, B1, sel);
        u32 hi16 = __byte_perm(B2, B3, sel);
        u32 M    = __byte_perm(lo16, hi16, 0x5410);

        // ---- layer 2: 8 nibble-LUT lookups, stride 10 (conflict-free v-banks) ----
        u64 h2 = b2p;
        h2 = add2(h2, *reinterpret_cast<const u64*>(tj + (M & 15u) * VSTR));
        h2 = add2(h2, *reinterpret_cast<const u64*>(tj + ((M >> 4)  & 15u) * VSTR + 160));
        h2 = add2(h2, *reinterpret_cast<const u64*>(tj + ((M >> 8)  & 15u) * VSTR + 320));
        h2 = add2(h2, *reinterpret_cast<const u64*>(tj + ((M >> 12) & 15u) * VSTR + 480));
        h2 = add2(h2, *reinterpret_cast<const u64*>(tj + ((M >> 16) & 15u) * VSTR + 640));
        h2 = add2(h2, *reinterpret_cast<const u64*>(tj + ((M >> 20) & 15u) * VSTR + 800));
        h2 = add2(h2, *reinterpret_cast<const u64*>(tj + ((M >> 24) & 15u) * VSTR + 960));
        h2 = add2(h2, *reinterpret_cast<const u64*>(tj + ((M >> 28) & 15u) * VSTR + 1120));

        // ---- IF layer 2 + rate accumulation ----
        v2p = add2(v2p, h2);
        float g0, g1; upk(g0, g1, v2p);
        bool t0 = (g0 >= 1.0f), t1 = (g1 >= 1.0f);
        accp = add2(accp, pk(t0 ? 1.0f : 0.0f, t1 ? 1.0f : 0.0f));
        v2p = pk(t0 ? 0.0f : g0, t1 ? 0.0f : g1);
    }

    // ---- output: lanes 0..19 write their (elem, j-pair) firing rates ----
    int ge = gbase + wid * EPW + me;
    if (lid < 20 && ge < B) {
        float a0, a1; upk(a0, a1, accp);
        *reinterpret_cast<float2*>(out + (size_t)ge * 10 + 2 * jj) =
            make_float2(a0 * (1.0f / 28.0f), a1 * (1.0f / 28.0f));
    }
}

extern "C" void kernel_launch(void* const* d_in, const int* in_sizes, int n_in,
                              void* d_out, int out_size) {
    const float* x  = (const float*)d_in[0];
    const float* W1 = (const float*)d_in[1];
    const float* b1 = (const float*)d_in[2];
    const float* W2 = (const float*)d_in[3];
    const float* b2 = (const float*)d_in[4];
    float* out = (float*)d_out;

    int B = in_sizes[0] / 784;
    int smem = SMEMW * (int)sizeof(float);   // 63,040 B -> 3 blocks/SM (12 warps)

    cudaFuncSetAttribute(snn_kernel, cudaFuncAttributeMaxDynamicSharedMemorySize, smem);

    int grid = (B + EPB - 1) / EPB;
    snn_kernel<<<grid, TPB, smem>>>(x, W1, b1, W2, b2, out, B);
}